// round 7
// baseline (speedup 1.0000x reference)
#include <cuda_runtime.h>
#include <cuda_bf16.h>

// DiceLoss fused single-kernel: softmax over C=19 + per-class dice reduction,
// last-block finalization (atomic ticket) + self-re-zeroing device accumulators.
// logits [8,19,512,512] f32; targets [8,512,512] int32.

#define CC      19
#define LOG_HW  18
#define HW      (1 << LOG_HW)        // 512*512
#define BATCH   8
#define NPIX    (BATCH * HW)         // 2,097,152
#define THREADS 256
#define NBLOCKS (NPIX / 4 / THREADS) // 2048 (4 pixels per thread)
#define IGN     255
#define CH0     10                   // class chunk sizes (front-batched loads)
#define CH1     9

__device__ float    g_ps[CC];  // per-class sum of probs over valid pixels
__device__ float    g_in[CC];  // per-class intersection
__device__ float    g_ct[CC];  // per-class valid counts
__device__ unsigned g_tick;    // block-completion ticket (ends each launch at 0)

__global__ void __launch_bounds__(THREADS, 2) dice_fused(
    const float* __restrict__ logits, const int* __restrict__ targets,
    float* __restrict__ out)
{
    __shared__ float s_ps[CC], s_in[CC], s_ct[CC];
    __shared__ int   s_last;
    const int tid = threadIdx.x;
    if (tid < CC) { s_ps[tid] = 0.f; s_in[tid] = 0.f; s_ct[tid] = 0.f; }
    __syncthreads();

    const int g  = blockIdx.x * THREADS + tid;
    const int p  = g << 2;                 // first pixel of this 4-pixel group
    const int b  = p >> LOG_HW;            // batch (groups never straddle b)
    const int hw = p & (HW - 1);
    const float* base = logits + (((size_t)b * CC) << LOG_HW) + hw;

    // ---- targets: 4 consecutive int32, one LDG.128 ----
    int4 t4 = *(const int4*)(targets + p);
    int t0 = t4.x, t1 = t4.y, t2 = t4.z, t3 = t4.w;
    float v0 = (t0 == IGN) ? 0.f : 1.f;
    float v1 = (t1 == IGN) ? 0.f : 1.f;
    float v2 = (t2 == IGN) ? 0.f : 1.f;
    float v3 = (t3 == IGN) ? 0.f : 1.f;
    t0 = (t0 == IGN || (unsigned)t0 >= CC) ? 0 : t0;
    t1 = (t1 == IGN || (unsigned)t1 >= CC) ? 0 : t1;
    t2 = (t2 == IGN || (unsigned)t2 >= CC) ? 0 : t2;
    t3 = (t3 == IGN || (unsigned)t3 >= CC) ? 0 : t3;

    // ---- per-class exps held as bf16x2 pairs (38 regs, not 76) ----
    __nv_bfloat162 e01[CC], e23[CC];
    float dx = 0.f, dy = 0.f, dz = 0.f, dw = 0.f;
    float ge0 = 0.f, ge1 = 0.f, ge2 = 0.f, ge3 = 0.f;

    {   // chunk 0: front-batch CH0 float4 loads (MLP ~ 10)
        float4 x[CH0];
        #pragma unroll
        for (int c = 0; c < CH0; c++)
            x[c] = *(const float4*)(base + ((size_t)c << LOG_HW));
        #pragma unroll
        for (int c = 0; c < CH0; c++) {
            float ex = __expf(x[c].x), ey = __expf(x[c].y);
            float ez = __expf(x[c].z), ew = __expf(x[c].w);
            dx += ex; dy += ey; dz += ez; dw += ew;
            if (c == t0) ge0 = ex;
            if (c == t1) ge1 = ey;
            if (c == t2) ge2 = ez;
            if (c == t3) ge3 = ew;
            e01[c] = __floats2bfloat162_rn(ex, ey);
            e23[c] = __floats2bfloat162_rn(ez, ew);
        }
    }
    {   // chunk 1: remaining CH1 classes
        float4 x[CH1];
        #pragma unroll
        for (int c = 0; c < CH1; c++)
            x[c] = *(const float4*)(base + ((size_t)(c + CH0) << LOG_HW));
        #pragma unroll
        for (int c = 0; c < CH1; c++) {
            const int cc = c + CH0;
            float ex = __expf(x[c].x), ey = __expf(x[c].y);
            float ez = __expf(x[c].z), ew = __expf(x[c].w);
            dx += ex; dy += ey; dz += ez; dw += ew;
            if (cc == t0) ge0 = ex;
            if (cc == t1) ge1 = ey;
            if (cc == t2) ge2 = ez;
            if (cc == t3) ge3 = ew;
            e01[cc] = __floats2bfloat162_rn(ex, ey);
            e23[cc] = __floats2bfloat162_rn(ez, ew);
        }
    }

    // validity folded into reciprocal: invalid pixels contribute exactly 0
    const float rx = v0 * __fdividef(1.f, dx);
    const float ry = v1 * __fdividef(1.f, dy);
    const float rz = v2 * __fdividef(1.f, dz);
    const float rw = v3 * __fdividef(1.f, dw);

    // ---- intersection / counts: shared atomics (fp32 gathered values) ----
    atomicAdd(&s_in[t0], ge0 * rx);
    atomicAdd(&s_in[t1], ge1 * ry);
    atomicAdd(&s_in[t2], ge2 * rz);
    atomicAdd(&s_in[t3], ge3 * rw);
    atomicAdd(&s_ct[t0], v0);
    atomicAdd(&s_ct[t1], v1);
    atomicAdd(&s_ct[t2], v2);
    atomicAdd(&s_ct[t3], v3);

    // ---- probs_sum: unpack bf16, FFMA, warp butterfly, shared ----
    #pragma unroll
    for (int c = 0; c < CC; c++) {
        float2 p01 = __bfloat1622float2(e01[c]);
        float2 p23 = __bfloat1622float2(e23[c]);
        float a = p01.x * rx + p01.y * ry + p23.x * rz + p23.y * rw;
        #pragma unroll
        for (int o = 16; o > 0; o >>= 1)
            a += __shfl_xor_sync(0xffffffffu, a, o);
        if ((tid & 31) == 0) atomicAdd(&s_ps[c], a);
    }
    __syncthreads();

    // ---- block -> global, with release fence before ticket ----
    if (tid < CC) {
        atomicAdd(&g_ps[tid], s_ps[tid]);
        atomicAdd(&g_in[tid], s_in[tid]);
        atomicAdd(&g_ct[tid], s_ct[tid]);
        __threadfence();
    }
    __syncthreads();
    if (tid == 0)
        s_last = (atomicAdd(&g_tick, 1u) == NBLOCKS - 1);
    __syncthreads();

    // ---- last block finalizes and re-zeros for the next graph replay ----
    if (s_last && tid < 32) {
        __threadfence();   // acquire
        float l = 0.f, cnt = 0.f;
        if (tid < CC) {
            float ps = *(volatile float*)&g_ps[tid];
            float in = *(volatile float*)&g_in[tid];
            float ct = *(volatile float*)&g_ct[tid];
            float dice = (2.f * in + 1.f) / (ps + ct + 1.f);
            l   = 1.f - dice;
            cnt = ct;
            *(volatile float*)&g_ps[tid] = 0.f;
            *(volatile float*)&g_in[tid] = 0.f;
            *(volatile float*)&g_ct[tid] = 0.f;
        }
        #pragma unroll
        for (int o = 16; o > 0; o >>= 1) {
            l   += __shfl_xor_sync(0xffffffffu, l, o);
            cnt += __shfl_xor_sync(0xffffffffu, cnt, o);
        }
        if (tid == 0) {
            out[0] = (cnt > 0.f) ? l * (1.f / CC) : 0.f;
            *(volatile unsigned*)&g_tick = 0u;
        }
    }
}

extern "C" void kernel_launch(void* const* d_in, const int* in_sizes, int n_in,
                              void* d_out, int out_size) {
    const float* logits  = (const float*)d_in[0];
    const int*   targets = (const int*)d_in[1];
    float*       out     = (float*)d_out;
    dice_fused<<<NBLOCKS, THREADS>>>(logits, targets, out);
}